// round 4
// baseline (speedup 1.0000x reference)
#include <cuda_runtime.h>
#include <cstdint>

// Problem constants
#define T_STEPS 200
#define HID     20
#define G4      80      // 4*HID gates
#define NPAIR   40      // packed f32x2 gate pairs
#define NTHR    128

// ---------- packed f32x2 helpers (Blackwell FFMA2; PTX-only) ----------
#define FMA2(d, a, b, c) \
    asm("fma.rn.f32x2 %0, %1, %2, %3;" : "=l"(d) : "l"(a), "l"(b), "l"(c))

__device__ __forceinline__ unsigned long long pack2(float x, float y) {
    unsigned long long r;
    asm("mov.b64 %0, {%1, %2};" : "=l"(r)
        : "r"(__float_as_uint(x)), "r"(__float_as_uint(y)));
    return r;
}
__device__ __forceinline__ void unpack2(unsigned long long v, float &x, float &y) {
    unsigned lo, hi;
    asm("mov.b64 {%0, %1}, %2;" : "=r"(lo), "=r"(hi) : "l"(v));
    x = __uint_as_float(lo);
    y = __uint_as_float(hi);
}

// ---------- fast activations (MUFU EX2+RCP, ~1e-6 rel err) ----------
__device__ __forceinline__ float sigm(float x) {
    return __fdividef(1.0f, 1.0f + __expf(-x));
}
__device__ __forceinline__ float tanh_fast(float x) {
    float ax = fabsf(x);
    float e  = __expf(-2.0f * ax);
    float r  = __fdividef(1.0f - e, 1.0f + e);
    return copysignf(r, x);
}

// ---------- exact JAX threefry2x32 (20 rounds) ----------
__device__ __forceinline__ void threefry2x32(unsigned k0, unsigned k1,
                                             unsigned x0, unsigned x1,
                                             unsigned &o0, unsigned &o1) {
    unsigned ks2 = k0 ^ k1 ^ 0x1BD11BDAu;
    x0 += k0; x1 += k1;
#define TFR(r) { x0 += x1; x1 = (x1 << r) | (x1 >> (32 - r)); x1 ^= x0; }
    TFR(13) TFR(15) TFR(26) TFR(6)
    x0 += k1;  x1 += ks2 + 1u;
    TFR(17) TFR(29) TFR(16) TFR(24)
    x0 += ks2; x1 += k0 + 2u;
    TFR(13) TFR(15) TFR(26) TFR(6)
    x0 += k0;  x1 += k1 + 3u;
    TFR(17) TFR(29) TFR(16) TFR(24)
    x0 += k1;  x1 += ks2 + 4u;
    TFR(13) TFR(15) TFR(26) TFR(6)
    x0 += ks2; x1 += k0 + 5u;
#undef TFR
    o0 = x0; o1 = x1;
}

// JAX partitionable-threefry random bits for flat index j (< 2^32):
// counter = (hi, lo) = (0, j); 32-bit output = o0 ^ o1.
__device__ __forceinline__ unsigned jax_random_bits_partitionable(unsigned j) {
    unsigned o0, o1;
    threefry2x32(0u, 42u, 0u, j, o0, o1);
    return o0 ^ o1;
}

__global__ void __launch_bounds__(NTHR, 1)
lstm_fused_kernel(const float* __restrict__ x,
                  const float* __restrict__ h0,
                  const float* __restrict__ c0,
                  const float* __restrict__ Wih0,
                  const float* __restrict__ Whh0,
                  const float* __restrict__ bih0,
                  const float* __restrict__ bhh0,
                  const float* __restrict__ Wih1,
                  const float* __restrict__ Whh1,
                  const float* __restrict__ bih1,
                  const float* __restrict__ bhh1,
                  const float* __restrict__ Wdec,
                  const float* __restrict__ bdec,
                  float* __restrict__ out,
                  int B) {
    // Weights pre-transposed + pair-packed: [k][p] holds (W[2p][k], W[2p+1][k])
    __shared__ __align__(16) float2 sWhh0[HID][NPAIR];
    __shared__ __align__(16) float2 sWih1[HID][NPAIR];
    __shared__ __align__(16) float2 sWhh1[HID][NPAIR];
    __shared__ __align__(16) float2 sW0a[NPAIR], sW0b[NPAIR];  // Wih0 cols 0/1 pair-packed
    __shared__ __align__(16) float2 sB0[NPAIR], sB1[NPAIR];    // combined biases pair-packed
    __shared__ float sHA[HID * NTHR];   // per-thread h slots, conflict-free
    __shared__ float sHB[HID * NTHR];

    const int tid = threadIdx.x;
    const int b   = blockIdx.x * NTHR + tid;

    for (int idx = tid; idx < HID * NPAIR; idx += NTHR) {
        int k = idx / NPAIR, p = idx - k * NPAIR;
        sWhh0[k][p] = make_float2(Whh0[(2 * p) * HID + k], Whh0[(2 * p + 1) * HID + k]);
        sWih1[k][p] = make_float2(Wih1[(2 * p) * HID + k], Wih1[(2 * p + 1) * HID + k]);
        sWhh1[k][p] = make_float2(Whh1[(2 * p) * HID + k], Whh1[(2 * p + 1) * HID + k]);
    }
    if (tid < NPAIR) {
        sW0a[tid] = make_float2(Wih0[(2 * tid) * 2 + 0], Wih0[(2 * tid + 1) * 2 + 0]);
        sW0b[tid] = make_float2(Wih0[(2 * tid) * 2 + 1], Wih0[(2 * tid + 1) * 2 + 1]);
        sB0[tid]  = make_float2(bih0[2 * tid]     + bhh0[2 * tid],
                                bih0[2 * tid + 1] + bhh0[2 * tid + 1]);
        sB1[tid]  = make_float2(bih1[2 * tid]     + bhh1[2 * tid],
                                bih1[2 * tid + 1] + bhh1[2 * tid + 1]);
    }
    __syncthreads();

    float cA[HID], cB[HID];
#pragma unroll
    for (int u = 0; u < HID; u++) {
        cA[u] = c0[(size_t)b * HID + u];
        cB[u] = c0[(size_t)B * HID + (size_t)b * HID + u];
        sHA[u * NTHR + tid] = h0[(size_t)b * HID + u];
        sHB[u * NTHR + tid] = h0[(size_t)B * HID + (size_t)b * HID + u];
    }

    // packed decoder accumulators (lane = h pair), folded at the end
    unsigned long long L0 = pack2(0.f, 0.f), L1 = L0, L2 = L0;

    const float2* x2 = reinterpret_cast<const float2*>(x);

#pragma unroll 1
    for (int t = 0; t < T_STEPS; t++) {
        float2 xv = x2[(size_t)t * B + b];
        unsigned long long xx = pack2(xv.x, xv.x);
        unsigned long long xy = pack2(xv.y, xv.y);

        unsigned long long gr[NPAIR];

        // -------- layer 1: input projection + bias --------
#pragma unroll
        for (int q = 0; q < NPAIR / 2; q++) {
            ulonglong2 wa = reinterpret_cast<const ulonglong2*>(sW0a)[q];
            ulonglong2 wb = reinterpret_cast<const ulonglong2*>(sW0b)[q];
            ulonglong2 bb = reinterpret_cast<const ulonglong2*>(sB0)[q];
            unsigned long long t0, t1;
            FMA2(t0, xy, wb.x, bb.x);  FMA2(gr[2 * q],     xx, wa.x, t0);
            FMA2(t1, xy, wb.y, bb.y);  FMA2(gr[2 * q + 1], xx, wa.y, t1);
        }
        // -------- layer 1: recurrent matvec --------
#pragma unroll 4
        for (int k = 0; k < HID; k++) {
            float hk = sHA[k * NTHR + tid];
            unsigned long long hk2 = pack2(hk, hk);
            const ulonglong2* row = reinterpret_cast<const ulonglong2*>(sWhh0[k]);
#pragma unroll
            for (int q = 0; q < NPAIR / 2; q++) {
                ulonglong2 w = row[q];
                FMA2(gr[2 * q],     hk2, w.x, gr[2 * q]);
                FMA2(gr[2 * q + 1], hk2, w.y, gr[2 * q + 1]);
            }
        }
        // -------- layer 1: cell update --------
#pragma unroll
        for (int p = 0; p < HID / 2; p++) {
            float i0, i1, f0, f1, g0, g1, o0, o1;
            unpack2(gr[p],      i0, i1);
            unpack2(gr[10 + p], f0, f1);
            unpack2(gr[20 + p], g0, g1);
            unpack2(gr[30 + p], o0, o1);
            float c0v = fmaf(sigm(f0), cA[2 * p],     sigm(i0) * tanh_fast(g0));
            float c1v = fmaf(sigm(f1), cA[2 * p + 1], sigm(i1) * tanh_fast(g1));
            cA[2 * p] = c0v;  cA[2 * p + 1] = c1v;
            sHA[(2 * p) * NTHR + tid]     = sigm(o0) * tanh_fast(c0v);
            sHA[(2 * p + 1) * NTHR + tid] = sigm(o1) * tanh_fast(c1v);
        }

        // -------- layer 2: bias init --------
#pragma unroll
        for (int q = 0; q < NPAIR / 2; q++) {
            ulonglong2 bb = reinterpret_cast<const ulonglong2*>(sB1)[q];
            gr[2 * q] = bb.x;  gr[2 * q + 1] = bb.y;
        }
        // -------- layer 2: input (h1) matvec --------
#pragma unroll 4
        for (int k = 0; k < HID; k++) {
            float hk = sHA[k * NTHR + tid];
            unsigned long long hk2 = pack2(hk, hk);
            const ulonglong2* row = reinterpret_cast<const ulonglong2*>(sWih1[k]);
#pragma unroll
            for (int q = 0; q < NPAIR / 2; q++) {
                ulonglong2 w = row[q];
                FMA2(gr[2 * q],     hk2, w.x, gr[2 * q]);
                FMA2(gr[2 * q + 1], hk2, w.y, gr[2 * q + 1]);
            }
        }
        // -------- layer 2: recurrent matvec --------
#pragma unroll 4
        for (int k = 0; k < HID; k++) {
            float hk = sHB[k * NTHR + tid];
            unsigned long long hk2 = pack2(hk, hk);
            const ulonglong2* row = reinterpret_cast<const ulonglong2*>(sWhh1[k]);
#pragma unroll
            for (int q = 0; q < NPAIR / 2; q++) {
                ulonglong2 w = row[q];
                FMA2(gr[2 * q],     hk2, w.x, gr[2 * q]);
                FMA2(gr[2 * q + 1], hk2, w.y, gr[2 * q + 1]);
            }
        }
        // -------- layer 2: cell update + fused packed decoder --------
        const float2* wd0 = reinterpret_cast<const float2*>(Wdec + t * HID);
        const float2* wd1 = reinterpret_cast<const float2*>(Wdec + T_STEPS * HID + t * HID);
        const float2* wd2 = reinterpret_cast<const float2*>(Wdec + 2 * T_STEPS * HID + t * HID);
#pragma unroll
        for (int p = 0; p < HID / 2; p++) {
            float i0, i1, f0, f1, g0, g1, o0, o1;
            unpack2(gr[p],      i0, i1);
            unpack2(gr[10 + p], f0, f1);
            unpack2(gr[20 + p], g0, g1);
            unpack2(gr[30 + p], o0, o1);
            float c0v = fmaf(sigm(f0), cB[2 * p],     sigm(i0) * tanh_fast(g0));
            float c1v = fmaf(sigm(f1), cB[2 * p + 1], sigm(i1) * tanh_fast(g1));
            cB[2 * p] = c0v;  cB[2 * p + 1] = c1v;
            float h0v = sigm(o0) * tanh_fast(c0v);
            float h1v = sigm(o1) * tanh_fast(c1v);
            sHB[(2 * p) * NTHR + tid]     = h0v;
            sHB[(2 * p + 1) * NTHR + tid] = h1v;
            unsigned long long hp = pack2(h0v, h1v);
            unsigned long long w0, w1, w2;
            { float2 w = wd0[p]; w0 = pack2(w.x, w.y); }
            { float2 w = wd1[p]; w1 = pack2(w.x, w.y); }
            { float2 w = wd2[p]; w2 = pack2(w.x, w.y); }
            FMA2(L0, hp, w0, L0);
            FMA2(L1, hp, w1, L1);
            FMA2(L2, hp, w2, L2);
        }
    }

    // fold packed decoder accumulators
    float la, lb;
    unpack2(L0, la, lb);  float logit0 = bdec[0] + la + lb;
    unpack2(L1, la, lb);  float logit1 = bdec[1] + la + lb;
    unpack2(L2, la, lb);  float logit2 = bdec[2] + la + lb;

    // -------- outputs: [action(B)] [slp(B)] [h_n(2,B,20)] [c_n(2,B,20)] --------
    float* o_h = out + 2 * (size_t)B;
    float* o_c = o_h + 2 * (size_t)B * HID;
#pragma unroll
    for (int u = 0; u < HID; u++) {
        o_h[(size_t)b * HID + u]                   = sHA[u * NTHR + tid];
        o_h[(size_t)B * HID + (size_t)b * HID + u] = sHB[u * NTHR + tid];
        o_c[(size_t)b * HID + u]                   = cA[u];
        o_c[(size_t)B * HID + (size_t)b * HID + u] = cB[u];
    }

    // log-softmax (accurate exp/log; executed once)
    float m   = fmaxf(logit0, fmaxf(logit1, logit2));
    float lse = m + logf(expf(logit0 - m) + expf(logit1 - m) + expf(logit2 - m));

    // categorical: Gumbel-argmax with JAX *partitionable* threefry, key (0,42).
    // element (b,a) flat index j=3b+a -> ctr (0,j), bits = o0^o1.
    const float tinyf = 1.17549435e-38f;
    float best = -1e30f, sel_logit = logit0;
    int act = 0;
#pragma unroll
    for (int a = 0; a < 3; a++) {
        unsigned bits = jax_random_bits_partitionable((unsigned)(b * 3 + a));
        float f  = __uint_as_float((bits >> 9) | 0x3f800000u) - 1.0f;
        float uu = fmaxf(tinyf, f + tinyf);
        float gmb = -logf(-logf(uu));
        float lg  = (a == 0) ? logit0 : (a == 1) ? logit1 : logit2;
        float v   = lg + gmb;
        if (v > best) { best = v; act = a; sel_logit = lg; }
    }
    out[b]     = (float)act;
    out[B + b] = sel_logit - lse;
}

extern "C" void kernel_launch(void* const* d_in, const int* in_sizes, int n_in,
                              void* d_out, int out_size) {
    const float* x    = (const float*)d_in[0];
    const float* h0   = (const float*)d_in[1];
    const float* c0   = (const float*)d_in[2];
    const float* Wih0 = (const float*)d_in[3];
    const float* Whh0 = (const float*)d_in[4];
    const float* bih0 = (const float*)d_in[5];
    const float* bhh0 = (const float*)d_in[6];
    const float* Wih1 = (const float*)d_in[7];
    const float* Whh1 = (const float*)d_in[8];
    const float* bih1 = (const float*)d_in[9];
    const float* bhh1 = (const float*)d_in[10];
    const float* Wdec = (const float*)d_in[11];
    const float* bdec = (const float*)d_in[12];

    int B = in_sizes[0] / (T_STEPS * 2);   // x is [T, B, 2]
    dim3 grid(B / NTHR), block(NTHR);
    lstm_fused_kernel<<<grid, block>>>(x, h0, c0, Wih0, Whh0, bih0, bhh0,
                                       Wih1, Whh1, bih1, bhh1, Wdec, bdec,
                                       (float*)d_out, B);
}

// round 5
// speedup vs baseline: 1.9884x; 1.9884x over previous
#include <cuda_runtime.h>
#include <cstdint>

#define T_STEPS 200
#define HID     20
#define NTHR    128      // 32 elements per block, 4 threads per element
#define EPB     32       // elements per block

// ---------- packed f32x2 helpers (Blackwell FFMA2; PTX-only) ----------
#define FMA2(d, a, b, c) \
    asm("fma.rn.f32x2 %0, %1, %2, %3;" : "=l"(d) : "l"(a), "l"(b), "l"(c))

__device__ __forceinline__ unsigned long long pack2(float x, float y) {
    unsigned long long r;
    asm("mov.b64 %0, {%1, %2};" : "=l"(r)
        : "r"(__float_as_uint(x)), "r"(__float_as_uint(y)));
    return r;
}
__device__ __forceinline__ void unpack2(unsigned long long v, float &x, float &y) {
    unsigned lo, hi;
    asm("mov.b64 {%0, %1}, %2;" : "=r"(lo), "=r"(hi) : "l"(v));
    x = __uint_as_float(lo);
    y = __uint_as_float(hi);
}

// ---------- fast activations (MUFU EX2+RCP, ~1e-6 rel err) ----------
__device__ __forceinline__ float sigm(float x) {
    return __fdividef(1.0f, 1.0f + __expf(-x));
}
__device__ __forceinline__ float tanh_fast(float x) {
    float ax = fabsf(x);
    float e  = __expf(-2.0f * ax);
    float r  = __fdividef(1.0f - e, 1.0f + e);
    return copysignf(r, x);
}

// ---------- exact JAX threefry2x32 (20 rounds) ----------
__device__ __forceinline__ void threefry2x32(unsigned k0, unsigned k1,
                                             unsigned x0, unsigned x1,
                                             unsigned &o0, unsigned &o1) {
    unsigned ks2 = k0 ^ k1 ^ 0x1BD11BDAu;
    x0 += k0; x1 += k1;
#define TFR(r) { x0 += x1; x1 = (x1 << r) | (x1 >> (32 - r)); x1 ^= x0; }
    TFR(13) TFR(15) TFR(26) TFR(6)
    x0 += k1;  x1 += ks2 + 1u;
    TFR(17) TFR(29) TFR(16) TFR(24)
    x0 += ks2; x1 += k0 + 2u;
    TFR(13) TFR(15) TFR(26) TFR(6)
    x0 += k0;  x1 += k1 + 3u;
    TFR(17) TFR(29) TFR(16) TFR(24)
    x0 += k1;  x1 += ks2 + 4u;
    TFR(13) TFR(15) TFR(26) TFR(6)
    x0 += ks2; x1 += k0 + 5u;
#undef TFR
    o0 = x0; o1 = x1;
}
// JAX partitionable threefry: ctr=(0,j), bits = o0^o1  (key (0,42))
__device__ __forceinline__ unsigned jax_random_bits_partitionable(unsigned j) {
    unsigned o0, o1;
    threefry2x32(0u, 42u, 0u, j, o0, o1);
    return o0 ^ o1;
}

// One k-contribution: 5 LDS.128 -> 10 FFMA2 over the thread's 10 gate pairs.
// gp[2q],gp[2q+1]: group q unit-pairs (5s,5s+1),(5s+2,5s+3) for q<4;
// gp[8]=(i_{5s+4}, f_{5s+4}), gp[9]=(g_{5s+4}, o_{5s+4}).
__device__ __forceinline__ void mv_accum(unsigned long long* gp, float hk,
                                         const float4* __restrict__ wrow) {
    unsigned long long h2 = pack2(hk, hk);
#pragma unroll
    for (int q = 0; q < 5; q++) {
        float4 v = wrow[q];
        unsigned long long lo = pack2(v.x, v.y), hi = pack2(v.z, v.w);
        FMA2(gp[2 * q],     h2, lo, gp[2 * q]);
        FMA2(gp[2 * q + 1], h2, hi, gp[2 * q + 1]);
    }
}

__device__ __forceinline__ void cell_update(unsigned long long* gp, float* c,
                                            float* hout) {
    float iv[5], fv[5], gv[5], ov[5];
    unpack2(gp[0], iv[0], iv[1]); unpack2(gp[1], iv[2], iv[3]);
    unpack2(gp[2], fv[0], fv[1]); unpack2(gp[3], fv[2], fv[3]);
    unpack2(gp[4], gv[0], gv[1]); unpack2(gp[5], gv[2], gv[3]);
    unpack2(gp[6], ov[0], ov[1]); unpack2(gp[7], ov[2], ov[3]);
    unpack2(gp[8], iv[4], fv[4]);
    unpack2(gp[9], gv[4], ov[4]);
#pragma unroll
    for (int j = 0; j < 5; j++) {
        float cv = fmaf(sigm(fv[j]), c[j], sigm(iv[j]) * tanh_fast(gv[j]));
        c[j] = cv;
        hout[j] = sigm(ov[j]) * tanh_fast(cv);
    }
}

__global__ void __launch_bounds__(NTHR, 4)
lstm_fused_kernel(const float* __restrict__ x,
                  const float* __restrict__ h0,
                  const float* __restrict__ c0,
                  const float* __restrict__ Wih0,
                  const float* __restrict__ Whh0,
                  const float* __restrict__ bih0,
                  const float* __restrict__ bhh0,
                  const float* __restrict__ Wih1,
                  const float* __restrict__ Whh1,
                  const float* __restrict__ bih1,
                  const float* __restrict__ bhh1,
                  const float* __restrict__ Wdec,
                  const float* __restrict__ bdec,
                  float* __restrict__ out,
                  int B) {
    // sW[m][k][sub][q]: m=0 Whh0, m=1 Wih1, m=2 Whh1 (gate-permuted float4 packs)
    __shared__ float4 sW[3][HID][4][5];
    __shared__ float4 sWx[2][4][5];      // Wih0 columns 0/1
    __shared__ float4 sBias[2][4][5];    // combined biases per layer
    __shared__ float  sHA[EPB][HID];
    __shared__ float  sHB[EPB][HID];

    const int tid = threadIdx.x;
    const int sub = tid & 3;            // thread-within-element
    const int e   = tid >> 2;           // block-local element
    const int b   = blockIdx.x * EPB + e;
    const int u0  = 5 * sub;            // first owned unit

    // ---------------- stage weights ----------------
    {
        const float* Wsrc[3] = {Whh0, Wih1, Whh1};
        for (int idx = tid; idx < 3 * HID * 4 * 5; idx += NTHR) {
            int m = idx / (HID * 20);
            int r = idx % (HID * 20);
            int k = r / 20;
            int s = (r % 20) / 5;
            int q = r % 5;
            const float* W = Wsrc[m];
            float4 v;
            if (q < 4) {
                int g = 20 * q + 5 * s;
                v = make_float4(W[(g + 0) * HID + k], W[(g + 1) * HID + k],
                                W[(g + 2) * HID + k], W[(g + 3) * HID + k]);
            } else {
                int u = 5 * s + 4;
                v = make_float4(W[u * HID + k],        W[(20 + u) * HID + k],
                                W[(40 + u) * HID + k], W[(60 + u) * HID + k]);
            }
            sW[m][k][s][q] = v;
        }
        for (int idx = tid; idx < 2 * 4 * 5; idx += NTHR) {
            int i = idx / 20, s = (idx % 20) / 5, q = idx % 5;
            float4 v;
            if (q < 4) {
                int g = 20 * q + 5 * s;
                v = make_float4(Wih0[(g + 0) * 2 + i], Wih0[(g + 1) * 2 + i],
                                Wih0[(g + 2) * 2 + i], Wih0[(g + 3) * 2 + i]);
            } else {
                int u = 5 * s + 4;
                v = make_float4(Wih0[u * 2 + i],        Wih0[(20 + u) * 2 + i],
                                Wih0[(40 + u) * 2 + i], Wih0[(60 + u) * 2 + i]);
            }
            sWx[i][s][q] = v;
        }
        for (int idx = tid; idx < 2 * 4 * 5; idx += NTHR) {
            int l = idx / 20, s = (idx % 20) / 5, q = idx % 5;
            const float* bi = l ? bih1 : bih0;
            const float* bh = l ? bhh1 : bhh0;
            float4 v;
            if (q < 4) {
                int g = 20 * q + 5 * s;
                v = make_float4(bi[g] + bh[g],         bi[g + 1] + bh[g + 1],
                                bi[g + 2] + bh[g + 2], bi[g + 3] + bh[g + 3]);
            } else {
                int u = 5 * s + 4;
                v = make_float4(bi[u] + bh[u],           bi[20 + u] + bh[20 + u],
                                bi[40 + u] + bh[40 + u], bi[60 + u] + bh[60 + u]);
            }
            sBias[l][s][q] = v;
        }
    }

    // ---------------- init state ----------------
    float cA[5], cB[5];
#pragma unroll
    for (int j = 0; j < 5; j++) {
        int u = u0 + j;
        cA[j] = c0[(size_t)b * HID + u];
        cB[j] = c0[(size_t)B * HID + (size_t)b * HID + u];
        sHA[e][u] = h0[(size_t)b * HID + u];
        sHB[e][u] = h0[(size_t)B * HID + (size_t)b * HID + u];
    }
    __syncthreads();

    float lg0 = 0.f, lg1 = 0.f, lg2 = 0.f;   // partial decoder logits
    float hB[5];                              // this thread's layer-2 h
    const float2* x2 = reinterpret_cast<const float2*>(x);

#pragma unroll 1
    for (int t = 0; t < T_STEPS; t++) {
        float2 xv = x2[(size_t)t * B + b];
        unsigned long long gp[10];

        // ---- layer 1: bias + input proj + recurrent matvec ----
#pragma unroll
        for (int q = 0; q < 5; q++) {
            float4 v = sBias[0][sub][q];
            gp[2 * q]     = pack2(v.x, v.y);
            gp[2 * q + 1] = pack2(v.z, v.w);
        }
        mv_accum(gp, xv.x, sWx[0][sub]);
        mv_accum(gp, xv.y, sWx[1][sub]);
#pragma unroll
        for (int k = 0; k < HID; k++)
            mv_accum(gp, sHA[e][k], sW[0][k][sub]);
        __syncwarp();
        float hA[5];
        cell_update(gp, cA, hA);
#pragma unroll
        for (int j = 0; j < 5; j++) sHA[e][u0 + j] = hA[j];
        __syncwarp();

        // ---- layer 2: bias + input(h1) matvec + recurrent matvec ----
#pragma unroll
        for (int q = 0; q < 5; q++) {
            float4 v = sBias[1][sub][q];
            gp[2 * q]     = pack2(v.x, v.y);
            gp[2 * q + 1] = pack2(v.z, v.w);
        }
#pragma unroll
        for (int k = 0; k < HID; k++)
            mv_accum(gp, sHA[e][k], sW[1][k][sub]);
#pragma unroll
        for (int k = 0; k < HID; k++)
            mv_accum(gp, sHB[e][k], sW[2][k][sub]);
        __syncwarp();
        cell_update(gp, cB, hB);
#pragma unroll
        for (int j = 0; j < 5; j++) sHB[e][u0 + j] = hB[j];
        __syncwarp();

        // ---- fused decoder partials (global loads, L1/L2 broadcast) ----
        const float* wd = Wdec + t * HID + u0;
#pragma unroll
        for (int j = 0; j < 5; j++) {
            lg0 = fmaf(hB[j], __ldg(wd + j),                       lg0);
            lg1 = fmaf(hB[j], __ldg(wd + T_STEPS * HID + j),       lg1);
            lg2 = fmaf(hB[j], __ldg(wd + 2 * T_STEPS * HID + j),   lg2);
        }
    }

    // ---------------- outputs ----------------
    float* o_h = out + 2 * (size_t)B;
    float* o_c = o_h + 2 * (size_t)B * HID;
#pragma unroll
    for (int j = 0; j < 5; j++) {
        int u = u0 + j;
        o_h[(size_t)b * HID + u]                   = sHA[e][u];
        o_h[(size_t)B * HID + (size_t)b * HID + u] = hB[j];
        o_c[(size_t)b * HID + u]                   = cA[j];
        o_c[(size_t)B * HID + (size_t)b * HID + u] = cB[j];
    }

    // reduce partial logits across the quad
#pragma unroll
    for (int off = 1; off < 4; off <<= 1) {
        lg0 += __shfl_xor_sync(0xffffffffu, lg0, off);
        lg1 += __shfl_xor_sync(0xffffffffu, lg1, off);
        lg2 += __shfl_xor_sync(0xffffffffu, lg2, off);
    }

    if (sub == 0) {
        float logit0 = lg0 + bdec[0];
        float logit1 = lg1 + bdec[1];
        float logit2 = lg2 + bdec[2];

        float m   = fmaxf(logit0, fmaxf(logit1, logit2));
        float lse = m + logf(expf(logit0 - m) + expf(logit1 - m) + expf(logit2 - m));

        const float tinyf = 1.17549435e-38f;
        float best = -1e30f, sel_logit = logit0;
        int act = 0;
#pragma unroll
        for (int a = 0; a < 3; a++) {
            unsigned bits = jax_random_bits_partitionable((unsigned)(b * 3 + a));
            float f  = __uint_as_float((bits >> 9) | 0x3f800000u) - 1.0f;
            float uu = fmaxf(tinyf, f + tinyf);
            float gmb = -logf(-logf(uu));
            float lg  = (a == 0) ? logit0 : (a == 1) ? logit1 : logit2;
            float v   = lg + gmb;
            if (v > best) { best = v; act = a; sel_logit = lg; }
        }
        out[b]     = (float)act;
        out[B + b] = sel_logit - lse;
    }
}

extern "C" void kernel_launch(void* const* d_in, const int* in_sizes, int n_in,
                              void* d_out, int out_size) {
    const float* x    = (const float*)d_in[0];
    const float* h0   = (const float*)d_in[1];
    const float* c0   = (const float*)d_in[2];
    const float* Wih0 = (const float*)d_in[3];
    const float* Whh0 = (const float*)d_in[4];
    const float* bih0 = (const float*)d_in[5];
    const float* bhh0 = (const float*)d_in[6];
    const float* Wih1 = (const float*)d_in[7];
    const float* Whh1 = (const float*)d_in[8];
    const float* bih1 = (const float*)d_in[9];
    const float* bhh1 = (const float*)d_in[10];
    const float* Wdec = (const float*)d_in[11];
    const float* bdec = (const float*)d_in[12];

    int B = in_sizes[0] / (T_STEPS * 2);   // x is [T, B, 2]
    dim3 grid(B / EPB), block(NTHR);
    lstm_fused_kernel<<<grid, block>>>(x, h0, c0, Wih0, Whh0, bih0, bhh0,
                                       Wih1, Whh1, bih1, bhh1, Wdec, bdec,
                                       (float*)d_out, B);
}

// round 6
// speedup vs baseline: 3.3481x; 1.6838x over previous
#include <cuda_runtime.h>
#include <cstdint>

#define T_STEPS 200
#define HID     20
#define NTHR    128      // 4 warps; warp = gate-quarter (sub), lane = element
#define EPB     32       // elements per block
#define HPAD    21       // padded hidden stride (coprime with 32 -> conflict-free)

// ---------- packed f32x2 helpers (Blackwell FFMA2; PTX-only) ----------
#define FMA2(d, a, b, c) \
    asm("fma.rn.f32x2 %0, %1, %2, %3;" : "=l"(d) : "l"(a), "l"(b), "l"(c))

__device__ __forceinline__ unsigned long long pack2(float x, float y) {
    unsigned long long r;
    asm("mov.b64 %0, {%1, %2};" : "=l"(r)
        : "r"(__float_as_uint(x)), "r"(__float_as_uint(y)));
    return r;
}
__device__ __forceinline__ void unpack2(unsigned long long v, float &x, float &y) {
    unsigned lo, hi;
    asm("mov.b64 {%0, %1}, %2;" : "=r"(lo), "=r"(hi) : "l"(v));
    x = __uint_as_float(lo);
    y = __uint_as_float(hi);
}

// ---------- fast activations (MUFU EX2+RCP, ~1e-6 rel err) ----------
__device__ __forceinline__ float sigm(float x) {
    return __fdividef(1.0f, 1.0f + __expf(-x));
}
__device__ __forceinline__ float tanh_fast(float x) {
    float ax = fabsf(x);
    float e  = __expf(-2.0f * ax);
    float r  = __fdividef(1.0f - e, 1.0f + e);
    return copysignf(r, x);
}

// ---------- exact JAX threefry2x32 (20 rounds) ----------
__device__ __forceinline__ void threefry2x32(unsigned k0, unsigned k1,
                                             unsigned x0, unsigned x1,
                                             unsigned &o0, unsigned &o1) {
    unsigned ks2 = k0 ^ k1 ^ 0x1BD11BDAu;
    x0 += k0; x1 += k1;
#define TFR(r) { x0 += x1; x1 = (x1 << r) | (x1 >> (32 - r)); x1 ^= x0; }
    TFR(13) TFR(15) TFR(26) TFR(6)
    x0 += k1;  x1 += ks2 + 1u;
    TFR(17) TFR(29) TFR(16) TFR(24)
    x0 += ks2; x1 += k0 + 2u;
    TFR(13) TFR(15) TFR(26) TFR(6)
    x0 += k0;  x1 += k1 + 3u;
    TFR(17) TFR(29) TFR(16) TFR(24)
    x0 += k1;  x1 += ks2 + 4u;
    TFR(13) TFR(15) TFR(26) TFR(6)
    x0 += ks2; x1 += k0 + 5u;
#undef TFR
    o0 = x0; o1 = x1;
}
// JAX partitionable threefry: ctr=(0,j), bits = o0^o1  (key (0,42))
__device__ __forceinline__ unsigned jax_random_bits_partitionable(unsigned j) {
    unsigned o0, o1;
    threefry2x32(0u, 42u, 0u, j, o0, o1);
    return o0 ^ o1;
}

// One k-contribution: 5 warp-uniform LDS.128 (broadcast) -> 10 FFMA2.
// float4 bit layout == two packed f32x2 operands, read directly as ulonglong2.
__device__ __forceinline__ void mv_accum(unsigned long long* gp, float hk,
                                         const float4* __restrict__ wrow) {
    unsigned long long h2 = pack2(hk, hk);
    const ulonglong2* r = reinterpret_cast<const ulonglong2*>(wrow);
#pragma unroll
    for (int q = 0; q < 5; q++) {
        ulonglong2 w = r[q];
        FMA2(gp[2 * q],     h2, w.x, gp[2 * q]);
        FMA2(gp[2 * q + 1], h2, w.y, gp[2 * q + 1]);
    }
}

// gp layout per thread (units u0..u0+4):
//  gp[2q],gp[2q+1] (q<4): gate-group q values for units (u0..u0+3)
//  gp[8]=(i4,f4), gp[9]=(g4,o4) for unit u0+4
__device__ __forceinline__ void cell_update(unsigned long long* gp, float* c,
                                            float* hout) {
    float iv[5], fv[5], gv[5], ov[5];
    unpack2(gp[0], iv[0], iv[1]); unpack2(gp[1], iv[2], iv[3]);
    unpack2(gp[2], fv[0], fv[1]); unpack2(gp[3], fv[2], fv[3]);
    unpack2(gp[4], gv[0], gv[1]); unpack2(gp[5], gv[2], gv[3]);
    unpack2(gp[6], ov[0], ov[1]); unpack2(gp[7], ov[2], ov[3]);
    unpack2(gp[8], iv[4], fv[4]);
    unpack2(gp[9], gv[4], ov[4]);
#pragma unroll
    for (int j = 0; j < 5; j++) {
        float cv = fmaf(sigm(fv[j]), c[j], sigm(iv[j]) * tanh_fast(gv[j]));
        c[j] = cv;
        hout[j] = sigm(ov[j]) * tanh_fast(cv);
    }
}

__global__ void __launch_bounds__(NTHR, 4)
lstm_fused_kernel(const float* __restrict__ x,
                  const float* __restrict__ h0,
                  const float* __restrict__ c0,
                  const float* __restrict__ Wih0,
                  const float* __restrict__ Whh0,
                  const float* __restrict__ bih0,
                  const float* __restrict__ bhh0,
                  const float* __restrict__ Wih1,
                  const float* __restrict__ Whh1,
                  const float* __restrict__ bih1,
                  const float* __restrict__ bhh1,
                  const float* __restrict__ Wdec,
                  const float* __restrict__ bdec,
                  float* __restrict__ out,
                  int B) {
    // sW[m][k][sub][q]: m=0 Whh0, m=1 Wih1, m=2 Whh1 (gate-permuted float4 packs)
    __shared__ float4 sW[3][HID][4][5];
    __shared__ float4 sWx[2][4][5];        // Wih0 columns 0/1
    __shared__ float4 sBias[2][4][5];      // combined biases per layer
    __shared__ float  sHA[2][EPB][HPAD];   // double-buffered layer-1 h
    __shared__ float  sHB[2][EPB][HPAD];   // double-buffered layer-2 h
    __shared__ float  sLG[3][4][EPB];      // decoder partial reduction scratch

    const int tid = threadIdx.x;
    const int sub = tid >> 5;           // warp id = gate quarter
    const int e   = tid & 31;           // lane = block-local element
    const int b   = blockIdx.x * EPB + e;
    const int u0  = 5 * sub;            // first owned unit

    // ---------------- stage weights ----------------
    {
        const float* Wsrc[3] = {Whh0, Wih1, Whh1};
        for (int idx = tid; idx < 3 * HID * 4 * 5; idx += NTHR) {
            int m = idx / (HID * 20);
            int r = idx % (HID * 20);
            int k = r / 20;
            int s = (r % 20) / 5;
            int q = r % 5;
            const float* W = Wsrc[m];
            float4 v;
            if (q < 4) {
                int g = 20 * q + 5 * s;
                v = make_float4(W[(g + 0) * HID + k], W[(g + 1) * HID + k],
                                W[(g + 2) * HID + k], W[(g + 3) * HID + k]);
            } else {
                int u = 5 * s + 4;
                v = make_float4(W[u * HID + k],        W[(20 + u) * HID + k],
                                W[(40 + u) * HID + k], W[(60 + u) * HID + k]);
            }
            sW[m][k][s][q] = v;
        }
        for (int idx = tid; idx < 2 * 4 * 5; idx += NTHR) {
            int i = idx / 20, s = (idx % 20) / 5, q = idx % 5;
            float4 v;
            if (q < 4) {
                int g = 20 * q + 5 * s;
                v = make_float4(Wih0[(g + 0) * 2 + i], Wih0[(g + 1) * 2 + i],
                                Wih0[(g + 2) * 2 + i], Wih0[(g + 3) * 2 + i]);
            } else {
                int u = 5 * s + 4;
                v = make_float4(Wih0[u * 2 + i],        Wih0[(20 + u) * 2 + i],
                                Wih0[(40 + u) * 2 + i], Wih0[(60 + u) * 2 + i]);
            }
            sWx[i][s][q] = v;
        }
        for (int idx = tid; idx < 2 * 4 * 5; idx += NTHR) {
            int l = idx / 20, s = (idx % 20) / 5, q = idx % 5;
            const float* bi = l ? bih1 : bih0;
            const float* bh = l ? bhh1 : bhh0;
            float4 v;
            if (q < 4) {
                int g = 20 * q + 5 * s;
                v = make_float4(bi[g] + bh[g],         bi[g + 1] + bh[g + 1],
                                bi[g + 2] + bh[g + 2], bi[g + 3] + bh[g + 3]);
            } else {
                int u = 5 * s + 4;
                v = make_float4(bi[u] + bh[u],           bi[20 + u] + bh[20 + u],
                                bi[40 + u] + bh[40 + u], bi[60 + u] + bh[60 + u]);
            }
            sBias[l][s][q] = v;
        }
    }

    // ---------------- init state ----------------
    float cA[5], cB[5], hA[5], hB[5];
#pragma unroll
    for (int j = 0; j < 5; j++) {
        int u = u0 + j;
        cA[j] = c0[(size_t)b * HID + u];
        cB[j] = c0[(size_t)B * HID + (size_t)b * HID + u];
        sHA[0][e][u] = h0[(size_t)b * HID + u];
        sHB[0][e][u] = h0[(size_t)B * HID + (size_t)b * HID + u];
    }
    __syncthreads();

    float lg0 = 0.f, lg1 = 0.f, lg2 = 0.f;   // partial decoder logits (5 units)
    const float2* x2 = reinterpret_cast<const float2*>(x);

#pragma unroll 1
    for (int t = 0; t < T_STEPS; t++) {
        const int cur = t & 1, nxt = cur ^ 1;
        float2 xv = x2[(size_t)t * B + b];
        unsigned long long gp[10];

        // ---- layer 1: bias + input proj + recurrent matvec ----
        {
            const ulonglong2* bb = reinterpret_cast<const ulonglong2*>(sBias[0][sub]);
#pragma unroll
            for (int q = 0; q < 5; q++) { gp[2 * q] = bb[q].x; gp[2 * q + 1] = bb[q].y; }
        }
        mv_accum(gp, xv.x, sWx[0][sub]);
        mv_accum(gp, xv.y, sWx[1][sub]);
#pragma unroll
        for (int k = 0; k < HID; k++)
            mv_accum(gp, sHA[cur][e][k], sW[0][k][sub]);
        cell_update(gp, cA, hA);
#pragma unroll
        for (int j = 0; j < 5; j++) sHA[nxt][e][u0 + j] = hA[j];
        __syncthreads();

        // ---- layer 2: bias + input(h1) matvec + recurrent matvec ----
        {
            const ulonglong2* bb = reinterpret_cast<const ulonglong2*>(sBias[1][sub]);
#pragma unroll
            for (int q = 0; q < 5; q++) { gp[2 * q] = bb[q].x; gp[2 * q + 1] = bb[q].y; }
        }
#pragma unroll
        for (int k = 0; k < HID; k++)
            mv_accum(gp, sHA[nxt][e][k], sW[1][k][sub]);
#pragma unroll
        for (int k = 0; k < HID; k++)
            mv_accum(gp, sHB[cur][e][k], sW[2][k][sub]);
        cell_update(gp, cB, hB);
#pragma unroll
        for (int j = 0; j < 5; j++) sHB[nxt][e][u0 + j] = hB[j];

        // ---- fused decoder partials (warp-uniform global loads -> L1 hit) ----
        const float* wd = Wdec + t * HID + u0;
#pragma unroll
        for (int j = 0; j < 5; j++) {
            lg0 = fmaf(hB[j], __ldg(wd + j),                     lg0);
            lg1 = fmaf(hB[j], __ldg(wd + T_STEPS * HID + j),     lg1);
            lg2 = fmaf(hB[j], __ldg(wd + 2 * T_STEPS * HID + j), lg2);
        }
        __syncthreads();
    }

    // ---------------- outputs ----------------
    float* o_h = out + 2 * (size_t)B;
    float* o_c = o_h + 2 * (size_t)B * HID;
#pragma unroll
    for (int j = 0; j < 5; j++) {
        int u = u0 + j;
        o_h[(size_t)b * HID + u]                   = hA[j];
        o_h[(size_t)B * HID + (size_t)b * HID + u] = hB[j];
        o_c[(size_t)b * HID + u]                   = cA[j];
        o_c[(size_t)B * HID + (size_t)b * HID + u] = cB[j];
    }

    // reduce decoder partials across the 4 warps
    sLG[0][sub][e] = lg0;
    sLG[1][sub][e] = lg1;
    sLG[2][sub][e] = lg2;
    __syncthreads();

    if (sub == 0) {
        float logit0 = sLG[0][0][e] + sLG[0][1][e] + sLG[0][2][e] + sLG[0][3][e] + bdec[0];
        float logit1 = sLG[1][0][e] + sLG[1][1][e] + sLG[1][2][e] + sLG[1][3][e] + bdec[1];
        float logit2 = sLG[2][0][e] + sLG[2][1][e] + sLG[2][2][e] + sLG[2][3][e] + bdec[2];

        float m   = fmaxf(logit0, fmaxf(logit1, logit2));
        float lse = m + logf(expf(logit0 - m) + expf(logit1 - m) + expf(logit2 - m));

        const float tinyf = 1.17549435e-38f;
        float best = -1e30f, sel_logit = logit0;
        int act = 0;
#pragma unroll
        for (int a = 0; a < 3; a++) {
            unsigned bits = jax_random_bits_partitionable((unsigned)(b * 3 + a));
            float f  = __uint_as_float((bits >> 9) | 0x3f800000u) - 1.0f;
            float uu = fmaxf(tinyf, f + tinyf);
            float gmb = -logf(-logf(uu));
            float lg  = (a == 0) ? logit0 : (a == 1) ? logit1 : logit2;
            float v   = lg + gmb;
            if (v > best) { best = v; act = a; sel_logit = lg; }
        }
        out[b]     = (float)act;
        out[B + b] = sel_logit - lse;
    }
}

extern "C" void kernel_launch(void* const* d_in, const int* in_sizes, int n_in,
                              void* d_out, int out_size) {
    const float* x    = (const float*)d_in[0];
    const float* h0   = (const float*)d_in[1];
    const float* c0   = (const float*)d_in[2];
    const float* Wih0 = (const float*)d_in[3];
    const float* Whh0 = (const float*)d_in[4];
    const float* bih0 = (const float*)d_in[5];
    const float* bhh0 = (const float*)d_in[6];
    const float* Wih1 = (const float*)d_in[7];
    const float* Whh1 = (const float*)d_in[8];
    const float* bih1 = (const float*)d_in[9];
    const float* bhh1 = (const float*)d_in[10];
    const float* Wdec = (const float*)d_in[11];
    const float* bdec = (const float*)d_in[12];

    int B = in_sizes[0] / (T_STEPS * 2);   // x is [T, B, 2]
    dim3 grid(B / EPB), block(NTHR);
    lstm_fused_kernel<<<grid, block>>>(x, h0, c0, Wih0, Whh0, bih0, bhh0,
                                       Wih1, Whh1, bih1, bhh1, Wdec, bdec,
                                       (float*)d_out, B);
}

// round 7
// speedup vs baseline: 3.8806x; 1.1591x over previous
#include <cuda_runtime.h>
#include <cstdint>

#define T_STEPS 200
#define HID     20
#define NTHR    128      // 4 warps; warp = gate-quarter (sub), lane = element pair
#define EPB     64       // elements per block (2 per thread: lane, lane+32)
#define HPAD    21       // padded hidden stride (odd -> conflict-free scalar access)

// ---------- packed f32x2 helpers (Blackwell FFMA2; PTX-only) ----------
#define FMA2(d, a, b, c) \
    asm("fma.rn.f32x2 %0, %1, %2, %3;" : "=l"(d) : "l"(a), "l"(b), "l"(c))

__device__ __forceinline__ unsigned long long pack2(float x, float y) {
    unsigned long long r;
    asm("mov.b64 %0, {%1, %2};" : "=l"(r)
        : "r"(__float_as_uint(x)), "r"(__float_as_uint(y)));
    return r;
}
__device__ __forceinline__ void unpack2(unsigned long long v, float &x, float &y) {
    unsigned lo, hi;
    asm("mov.b64 {%0, %1}, %2;" : "=r"(lo), "=r"(hi) : "l"(v));
    x = __uint_as_float(lo);
    y = __uint_as_float(hi);
}

// ---------- fast activations (MUFU EX2+RCP, ~1e-6 rel err) ----------
__device__ __forceinline__ float sigm(float x) {
    return __fdividef(1.0f, 1.0f + __expf(-x));
}
__device__ __forceinline__ float tanh_fast(float x) {
    float ax = fabsf(x);
    float e  = __expf(-2.0f * ax);
    float r  = __fdividef(1.0f - e, 1.0f + e);
    return copysignf(r, x);
}

// ---------- exact JAX threefry2x32 (20 rounds) ----------
__device__ __forceinline__ void threefry2x32(unsigned k0, unsigned k1,
                                             unsigned x0, unsigned x1,
                                             unsigned &o0, unsigned &o1) {
    unsigned ks2 = k0 ^ k1 ^ 0x1BD11BDAu;
    x0 += k0; x1 += k1;
#define TFR(r) { x0 += x1; x1 = (x1 << r) | (x1 >> (32 - r)); x1 ^= x0; }
    TFR(13) TFR(15) TFR(26) TFR(6)
    x0 += k1;  x1 += ks2 + 1u;
    TFR(17) TFR(29) TFR(16) TFR(24)
    x0 += ks2; x1 += k0 + 2u;
    TFR(13) TFR(15) TFR(26) TFR(6)
    x0 += k0;  x1 += k1 + 3u;
    TFR(17) TFR(29) TFR(16) TFR(24)
    x0 += k1;  x1 += ks2 + 4u;
    TFR(13) TFR(15) TFR(26) TFR(6)
    x0 += ks2; x1 += k0 + 5u;
#undef TFR
    o0 = x0; o1 = x1;
}
// JAX partitionable threefry: ctr=(0,j), bits = o0^o1  (key (0,42))
__device__ __forceinline__ unsigned jax_random_bits_partitionable(unsigned j) {
    unsigned o0, o1;
    threefry2x32(0u, 42u, 0u, j, o0, o1);
    return o0 ^ o1;
}

// One k-contribution for TWO elements: 5 broadcast LDS.128 -> 20 FFMA2.
__device__ __forceinline__ void mv_accum2(unsigned long long* gpa,
                                          unsigned long long* gpb,
                                          float ha, float hb,
                                          const float4* __restrict__ wrow) {
    unsigned long long h2a = pack2(ha, ha);
    unsigned long long h2b = pack2(hb, hb);
    const ulonglong2* r = reinterpret_cast<const ulonglong2*>(wrow);
#pragma unroll
    for (int q = 0; q < 5; q++) {
        ulonglong2 w = r[q];
        FMA2(gpa[2 * q],     h2a, w.x, gpa[2 * q]);
        FMA2(gpa[2 * q + 1], h2a, w.y, gpa[2 * q + 1]);
        FMA2(gpb[2 * q],     h2b, w.x, gpb[2 * q]);
        FMA2(gpb[2 * q + 1], h2b, w.y, gpb[2 * q + 1]);
    }
}

// gp layout per element (units u0..u0+4):
//  gp[2q],gp[2q+1] (q<4): gate-group q values for units (u0..u0+3)
//  gp[8]=(i4,f4), gp[9]=(g4,o4) for unit u0+4
__device__ __forceinline__ void cell_update(unsigned long long* gp, float* c,
                                            float* hout) {
    float iv[5], fv[5], gv[5], ov[5];
    unpack2(gp[0], iv[0], iv[1]); unpack2(gp[1], iv[2], iv[3]);
    unpack2(gp[2], fv[0], fv[1]); unpack2(gp[3], fv[2], fv[3]);
    unpack2(gp[4], gv[0], gv[1]); unpack2(gp[5], gv[2], gv[3]);
    unpack2(gp[6], ov[0], ov[1]); unpack2(gp[7], ov[2], ov[3]);
    unpack2(gp[8], iv[4], fv[4]);
    unpack2(gp[9], gv[4], ov[4]);
#pragma unroll
    for (int j = 0; j < 5; j++) {
        float cv = fmaf(sigm(fv[j]), c[j], sigm(iv[j]) * tanh_fast(gv[j]));
        c[j] = cv;
        hout[j] = sigm(ov[j]) * tanh_fast(cv);
    }
}

__global__ void __launch_bounds__(NTHR, 2)
lstm_fused_kernel(const float* __restrict__ x,
                  const float* __restrict__ h0,
                  const float* __restrict__ c0,
                  const float* __restrict__ Wih0,
                  const float* __restrict__ Whh0,
                  const float* __restrict__ bih0,
                  const float* __restrict__ bhh0,
                  const float* __restrict__ Wih1,
                  const float* __restrict__ Whh1,
                  const float* __restrict__ bih1,
                  const float* __restrict__ bhh1,
                  const float* __restrict__ Wdec,
                  const float* __restrict__ bdec,
                  float* __restrict__ out,
                  int B) {
    // sW[m][k][sub][q]: m=0 Whh0, m=1 Wih1, m=2 Whh1 (gate-permuted float4 packs)
    __shared__ float4 sW[3][HID][4][5];
    __shared__ float4 sWx[2][4][5];        // Wih0 columns 0/1
    __shared__ float4 sBias[2][4][5];      // combined biases per layer
    __shared__ float  sHA[2][EPB][HPAD];   // double-buffered layer-1 h
    __shared__ float  sHB[2][EPB][HPAD];   // double-buffered layer-2 h
    __shared__ float  sLG[3][4][EPB];      // decoder partial reduction scratch

    const int tid = threadIdx.x;
    const int sub = tid >> 5;           // warp id = gate quarter
    const int e0  = tid & 31;           // first element (block-local)
    const int e1  = e0 + 32;            // second element
    const int b0  = blockIdx.x * EPB + e0;
    const int b1  = b0 + 32;
    const int u0  = 5 * sub;            // first owned unit

    // ---------------- stage weights ----------------
    {
        const float* Wsrc[3] = {Whh0, Wih1, Whh1};
        for (int idx = tid; idx < 3 * HID * 4 * 5; idx += NTHR) {
            int m = idx / (HID * 20);
            int r = idx % (HID * 20);
            int k = r / 20;
            int s = (r % 20) / 5;
            int q = r % 5;
            const float* W = Wsrc[m];
            float4 v;
            if (q < 4) {
                int g = 20 * q + 5 * s;
                v = make_float4(W[(g + 0) * HID + k], W[(g + 1) * HID + k],
                                W[(g + 2) * HID + k], W[(g + 3) * HID + k]);
            } else {
                int u = 5 * s + 4;
                v = make_float4(W[u * HID + k],        W[(20 + u) * HID + k],
                                W[(40 + u) * HID + k], W[(60 + u) * HID + k]);
            }
            sW[m][k][s][q] = v;
        }
        for (int idx = tid; idx < 2 * 4 * 5; idx += NTHR) {
            int i = idx / 20, s = (idx % 20) / 5, q = idx % 5;
            float4 v;
            if (q < 4) {
                int g = 20 * q + 5 * s;
                v = make_float4(Wih0[(g + 0) * 2 + i], Wih0[(g + 1) * 2 + i],
                                Wih0[(g + 2) * 2 + i], Wih0[(g + 3) * 2 + i]);
            } else {
                int u = 5 * s + 4;
                v = make_float4(Wih0[u * 2 + i],        Wih0[(20 + u) * 2 + i],
                                Wih0[(40 + u) * 2 + i], Wih0[(60 + u) * 2 + i]);
            }
            sWx[i][s][q] = v;
        }
        for (int idx = tid; idx < 2 * 4 * 5; idx += NTHR) {
            int l = idx / 20, s = (idx % 20) / 5, q = idx % 5;
            const float* bi = l ? bih1 : bih0;
            const float* bh = l ? bhh1 : bhh0;
            float4 v;
            if (q < 4) {
                int g = 20 * q + 5 * s;
                v = make_float4(bi[g] + bh[g],         bi[g + 1] + bh[g + 1],
                                bi[g + 2] + bh[g + 2], bi[g + 3] + bh[g + 3]);
            } else {
                int u = 5 * s + 4;
                v = make_float4(bi[u] + bh[u],           bi[20 + u] + bh[20 + u],
                                bi[40 + u] + bh[40 + u], bi[60 + u] + bh[60 + u]);
            }
            sBias[l][s][q] = v;
        }
    }

    // ---------------- init state ----------------
    float cA[2][5], cB[2][5], hA[2][5], hB[2][5];
#pragma unroll
    for (int j = 0; j < 5; j++) {
        int u = u0 + j;
        cA[0][j] = c0[(size_t)b0 * HID + u];
        cA[1][j] = c0[(size_t)b1 * HID + u];
        cB[0][j] = c0[(size_t)B * HID + (size_t)b0 * HID + u];
        cB[1][j] = c0[(size_t)B * HID + (size_t)b1 * HID + u];
        sHA[0][e0][u] = h0[(size_t)b0 * HID + u];
        sHA[0][e1][u] = h0[(size_t)b1 * HID + u];
        sHB[0][e0][u] = h0[(size_t)B * HID + (size_t)b0 * HID + u];
        sHB[0][e1][u] = h0[(size_t)B * HID + (size_t)b1 * HID + u];
    }
    __syncthreads();

    float lg[2][3] = {{0.f, 0.f, 0.f}, {0.f, 0.f, 0.f}};
    const float2* x2 = reinterpret_cast<const float2*>(x);

#pragma unroll 1
    for (int t = 0; t < T_STEPS; t++) {
        const int cur = t & 1, nxt = cur ^ 1;
        float2 xv0 = x2[(size_t)t * B + b0];
        float2 xv1 = x2[(size_t)t * B + b1];
        unsigned long long gpa[10], gpb[10];

        // ---- layer 1: bias + input proj + recurrent matvec ----
        {
            const ulonglong2* bb = reinterpret_cast<const ulonglong2*>(sBias[0][sub]);
#pragma unroll
            for (int q = 0; q < 5; q++) {
                gpa[2 * q] = bb[q].x;  gpa[2 * q + 1] = bb[q].y;
                gpb[2 * q] = bb[q].x;  gpb[2 * q + 1] = bb[q].y;
            }
        }
        mv_accum2(gpa, gpb, xv0.x, xv1.x, sWx[0][sub]);
        mv_accum2(gpa, gpb, xv0.y, xv1.y, sWx[1][sub]);
        {
            const float4* wbase = &sW[0][0][sub][0];
#pragma unroll 5
            for (int k = 0; k < HID; k++)
                mv_accum2(gpa, gpb, sHA[cur][e0][k], sHA[cur][e1][k],
                          wbase + (size_t)k * 20);
        }
        cell_update(gpa, cA[0], hA[0]);
        cell_update(gpb, cA[1], hA[1]);
#pragma unroll
        for (int j = 0; j < 5; j++) {
            sHA[nxt][e0][u0 + j] = hA[0][j];
            sHA[nxt][e1][u0 + j] = hA[1][j];
        }
        __syncthreads();

        // ---- layer 2: bias + input(h1) matvec + recurrent matvec ----
        {
            const ulonglong2* bb = reinterpret_cast<const ulonglong2*>(sBias[1][sub]);
#pragma unroll
            for (int q = 0; q < 5; q++) {
                gpa[2 * q] = bb[q].x;  gpa[2 * q + 1] = bb[q].y;
                gpb[2 * q] = bb[q].x;  gpb[2 * q + 1] = bb[q].y;
            }
        }
        {
            const float4* wbase = &sW[1][0][sub][0];
#pragma unroll 5
            for (int k = 0; k < HID; k++)
                mv_accum2(gpa, gpb, sHA[nxt][e0][k], sHA[nxt][e1][k],
                          wbase + (size_t)k * 20);
        }
        {
            const float4* wbase = &sW[2][0][sub][0];
#pragma unroll 5
            for (int k = 0; k < HID; k++)
                mv_accum2(gpa, gpb, sHB[cur][e0][k], sHB[cur][e1][k],
                          wbase + (size_t)k * 20);
        }
        cell_update(gpa, cB[0], hB[0]);
        cell_update(gpb, cB[1], hB[1]);
#pragma unroll
        for (int j = 0; j < 5; j++) {
            sHB[nxt][e0][u0 + j] = hB[0][j];
            sHB[nxt][e1][u0 + j] = hB[1][j];
        }

        // ---- fused decoder partials (warp-uniform loads serve both elements) ----
        const float* wd = Wdec + t * HID + u0;
#pragma unroll
        for (int j = 0; j < 5; j++) {
            float w0 = __ldg(wd + j);
            float w1 = __ldg(wd + T_STEPS * HID + j);
            float w2 = __ldg(wd + 2 * T_STEPS * HID + j);
            lg[0][0] = fmaf(hB[0][j], w0, lg[0][0]);
            lg[0][1] = fmaf(hB[0][j], w1, lg[0][1]);
            lg[0][2] = fmaf(hB[0][j], w2, lg[0][2]);
            lg[1][0] = fmaf(hB[1][j], w0, lg[1][0]);
            lg[1][1] = fmaf(hB[1][j], w1, lg[1][1]);
            lg[1][2] = fmaf(hB[1][j], w2, lg[1][2]);
        }
        __syncthreads();
    }

    // ---------------- outputs ----------------
    float* o_h = out + 2 * (size_t)B;
    float* o_c = o_h + 2 * (size_t)B * HID;
#pragma unroll
    for (int j = 0; j < 5; j++) {
        int u = u0 + j;
        o_h[(size_t)b0 * HID + u]                   = hA[0][j];
        o_h[(size_t)b1 * HID + u]                   = hA[1][j];
        o_h[(size_t)B * HID + (size_t)b0 * HID + u] = hB[0][j];
        o_h[(size_t)B * HID + (size_t)b1 * HID + u] = hB[1][j];
        o_c[(size_t)b0 * HID + u]                   = cA[0][j];
        o_c[(size_t)b1 * HID + u]                   = cA[1][j];
        o_c[(size_t)B * HID + (size_t)b0 * HID + u] = cB[0][j];
        o_c[(size_t)B * HID + (size_t)b1 * HID + u] = cB[1][j];
    }

    // reduce decoder partials across the 4 warps
#pragma unroll
    for (int a = 0; a < 3; a++) {
        sLG[a][sub][e0] = lg[0][a];
        sLG[a][sub][e1] = lg[1][a];
    }
    __syncthreads();

    if (sub == 0) {
#pragma unroll
        for (int ei = 0; ei < 2; ei++) {
            int e = (ei == 0) ? e0 : e1;
            int b = (ei == 0) ? b0 : b1;
            float logit0 = sLG[0][0][e] + sLG[0][1][e] + sLG[0][2][e] + sLG[0][3][e] + bdec[0];
            float logit1 = sLG[1][0][e] + sLG[1][1][e] + sLG[1][2][e] + sLG[1][3][e] + bdec[1];
            float logit2 = sLG[2][0][e] + sLG[2][1][e] + sLG[2][2][e] + sLG[2][3][e] + bdec[2];

            float m   = fmaxf(logit0, fmaxf(logit1, logit2));
            float lse = m + logf(expf(logit0 - m) + expf(logit1 - m) + expf(logit2 - m));

            const float tinyf = 1.17549435e-38f;
            float best = -1e30f, sel_logit = logit0;
            int act = 0;
#pragma unroll
            for (int a = 0; a < 3; a++) {
                unsigned bits = jax_random_bits_partitionable((unsigned)(b * 3 + a));
                float f  = __uint_as_float((bits >> 9) | 0x3f800000u) - 1.0f;
                float uu = fmaxf(tinyf, f + tinyf);
                float gmb = -logf(-logf(uu));
                float lgv = (a == 0) ? logit0 : (a == 1) ? logit1 : logit2;
                float v   = lgv + gmb;
                if (v > best) { best = v; act = a; sel_logit = lgv; }
            }
            out[b]     = (float)act;
            out[B + b] = sel_logit - lse;
        }
    }
}

extern "C" void kernel_launch(void* const* d_in, const int* in_sizes, int n_in,
                              void* d_out, int out_size) {
    const float* x    = (const float*)d_in[0];
    const float* h0   = (const float*)d_in[1];
    const float* c0   = (const float*)d_in[2];
    const float* Wih0 = (const float*)d_in[3];
    const float* Whh0 = (const float*)d_in[4];
    const float* bih0 = (const float*)d_in[5];
    const float* bhh0 = (const float*)d_in[6];
    const float* Wih1 = (const float*)d_in[7];
    const float* Whh1 = (const float*)d_in[8];
    const float* bih1 = (const float*)d_in[9];
    const float* bhh1 = (const float*)d_in[10];
    const float* Wdec = (const float*)d_in[11];
    const float* bdec = (const float*)d_in[12];

    int B = in_sizes[0] / (T_STEPS * 2);   // x is [T, B, 2]
    dim3 grid(B / EPB), block(NTHR);
    lstm_fused_kernel<<<grid, block>>>(x, h0, c0, Wih0, Whh0, bih0, bhh0,
                                       Wih1, Whh1, bih1, bhh1, Wdec, bdec,
                                       (float*)d_out, B);
}